// round 13
// baseline (speedup 1.0000x reference)
#include <cuda_runtime.h>
#include <cuda_bf16.h>
#include <cuda_fp16.h>
#include <cstdint>

#define NN   50000
#define FIN  256
#define HH   4
#define CC   32
#define HC   128
#define EMAX 1600000

// ---------------- scratch (static __device__, no allocations) ----------------
__device__ __half g_hh[(size_t)NN * HC];  // dropout(x) @ W  in fp16 (12.8 MB)
__device__ float  g_as[NN * HH];          // <h, att_src>
__device__ float  g_ad[NN * HH];          // <h, att_dst>
__device__ int    g_rowptr[NN + 1];       // CSR row pointers (by dst)
__device__ int    g_cnt[NN];              // degree counters / write cursors
__device__ int    g_srcs[EMAX + NN];      // CSR: src node per incoming edge

// JAX partitionable threefry dropout factor for element index i:
// (b1,b2) = threefry2x32(key=(0,1), x0=0, x1=i); bits = b1^b2
// keep if bitcast((bits>>9)|0x3f800000)-1 < 0.8  ->  * 1.25, else 0
__device__ __forceinline__ float drop_factor(unsigned i) {
    unsigned x0 = 0u, x1 = i;
    const unsigned ks0 = 0u, ks1 = 1u, ks2 = 0x1BD11BDBu;
    x0 += ks0; x1 += ks1;
#define TF_R(r) { x0 += x1; x1 = (x1 << (r)) | (x1 >> (32 - (r))); x1 ^= x0; }
    TF_R(13) TF_R(15) TF_R(26) TF_R(6)   x0 += ks1; x1 += ks2 + 1u;
    TF_R(17) TF_R(29) TF_R(16) TF_R(24)  x0 += ks2; x1 += ks0 + 2u;
    TF_R(13) TF_R(15) TF_R(26) TF_R(6)   x0 += ks0; x1 += ks1 + 3u;
    TF_R(17) TF_R(29) TF_R(16) TF_R(24)  x0 += ks1; x1 += ks2 + 4u;
    TF_R(13) TF_R(15) TF_R(26) TF_R(6)   x0 += ks2; x1 += ks0 + 5u;
#undef TF_R
    unsigned bits = x0 ^ x1;
    float u = __uint_as_float((bits >> 9) | 0x3F800000u) - 1.0f;
    return (u < 0.8f) ? 1.25f : 0.0f;
}

// ---------------- CSR build ----------------
__global__ void k_cnt_init(int n) {
    int i = blockIdx.x * blockDim.x + threadIdx.x;
    if (i < n) g_cnt[i] = 1;             // 1 = the self-loop
}
__global__ void k_hist(const int* __restrict__ ei, int E) {
    int e = blockIdx.x * blockDim.x + threadIdx.x;
    if (e < E) atomicAdd(&g_cnt[ei[E + e]], 1);
}
// single-block scan -> exclusive rowptr; g_cnt becomes write cursor
__global__ void k_scan(int n) {
    __shared__ int part[1024];
    const int tid = threadIdx.x;
    const int chunk = (n + 1023) / 1024;
    const int lo = tid * chunk;
    const int hi = min(lo + chunk, n);
    int sum = 0;
    for (int i = lo; i < hi; i++) sum += g_cnt[i];
    part[tid] = sum;
    __syncthreads();
    for (int off = 1; off < 1024; off <<= 1) {
        int v = 0;
        if (tid >= off) v = part[tid - off];
        __syncthreads();
        if (tid >= off) part[tid] += v;
        __syncthreads();
    }
    int run = (tid == 0) ? 0 : part[tid - 1];
    for (int i = lo; i < hi; i++) {
        int c = g_cnt[i];
        g_rowptr[i] = run;
        g_cnt[i]    = run;               // cursor for scatter
        run += c;
    }
    if (tid == 1023) g_rowptr[n] = part[1023];
}
__global__ void k_scatter(const int* __restrict__ ei, int E, int n) {
    int e = blockIdx.x * blockDim.x + threadIdx.x;
    if (e >= E + n) return;
    int s, d;
    if (e < E) { s = ei[e]; d = ei[E + e]; }
    else       { s = d = e - E; }
    int pos = atomicAdd(&g_cnt[d], 1);
    g_srcs[pos] = s;
}

// ---------------- SGEMM: fused dropout, double-buffered, fused att logits ---
// h = dropout(x) @ W ; stores h as fp16; epilogue computes g_as/g_ad in fp32
__global__ void k_gemm(const float* __restrict__ X, const float* __restrict__ W,
                       const float* __restrict__ att_src,
                       const float* __restrict__ att_dst, int M) {
    __shared__ float As[2][16][128];
    __shared__ float Bs[2][16][128];
    const int bm  = blockIdx.x * 128;
    const int tid = threadIdx.x;

    const int arow = tid >> 2;          // 0..63
    const int acol = (tid & 3) << 2;    // 0,4,8,12
    const int brow = tid >> 5;          // 0..7
    const int bcol = (tid & 31) << 2;   // 0..124

    const int tx = (tid & 15) << 3;     // out col base
    const int ty = (tid >> 4) << 3;     // out row base (within tile)

    const int rowA0 = bm + arow;
    const int rowA1 = bm + arow + 64;

    float acc[8][8];
#pragma unroll
    for (int i = 0; i < 8; i++)
#pragma unroll
        for (int j = 0; j < 8; j++) acc[i][j] = 0.0f;

    float4 aN[2], bN[2];

#pragma unroll
    for (int r = 0; r < 2; r++) {
        int row = r ? rowA1 : rowA0;
        aN[r] = make_float4(0.f, 0.f, 0.f, 0.f);
        if (row < M) {
            aN[r] = *(const float4*)&X[(size_t)row * 256 + acol];
            unsigned base = (unsigned)row * 256u + (unsigned)acol;
            aN[r].x *= drop_factor(base + 0u);
            aN[r].y *= drop_factor(base + 1u);
            aN[r].z *= drop_factor(base + 2u);
            aN[r].w *= drop_factor(base + 3u);
        }
        bN[r] = *(const float4*)&W[(size_t)(brow + r * 8) * 128 + bcol];
    }
#pragma unroll
    for (int r = 0; r < 2; r++) {
        As[0][acol + 0][arow + r * 64] = aN[r].x;
        As[0][acol + 1][arow + r * 64] = aN[r].y;
        As[0][acol + 2][arow + r * 64] = aN[r].z;
        As[0][acol + 3][arow + r * 64] = aN[r].w;
        *(float4*)&Bs[0][brow + r * 8][bcol] = bN[r];
    }
    __syncthreads();

    for (int kt_i = 0; kt_i < 16; kt_i++) {
        const int cur = kt_i & 1;
        if (kt_i < 15) {
            const int kt = (kt_i + 1) * 16;
#pragma unroll
            for (int r = 0; r < 2; r++) {
                int row = r ? rowA1 : rowA0;
                aN[r] = make_float4(0.f, 0.f, 0.f, 0.f);
                if (row < M) aN[r] = *(const float4*)&X[(size_t)row * 256 + kt + acol];
                bN[r] = *(const float4*)&W[(size_t)(kt + brow + r * 8) * 128 + bcol];
            }
        }

#pragma unroll
        for (int k = 0; k < 16; k++) {
            float4 a0 = *(float4*)&As[cur][k][ty];
            float4 a1 = *(float4*)&As[cur][k][ty + 4];
            float4 b0 = *(float4*)&Bs[cur][k][tx];
            float4 b1 = *(float4*)&Bs[cur][k][tx + 4];
            float ar[8] = {a0.x, a0.y, a0.z, a0.w, a1.x, a1.y, a1.z, a1.w};
            float br[8] = {b0.x, b0.y, b0.z, b0.w, b1.x, b1.y, b1.z, b1.w};
#pragma unroll
            for (int i = 0; i < 8; i++)
#pragma unroll
                for (int j = 0; j < 8; j++) acc[i][j] += ar[i] * br[j];
        }

        if (kt_i < 15) {
            const int kt = (kt_i + 1) * 16;
            const int nxt = cur ^ 1;
#pragma unroll
            for (int r = 0; r < 2; r++) {
                int row = r ? rowA1 : rowA0;
                if (row < M) {
                    unsigned base = (unsigned)row * 256u + (unsigned)(kt + acol);
                    aN[r].x *= drop_factor(base + 0u);
                    aN[r].y *= drop_factor(base + 1u);
                    aN[r].z *= drop_factor(base + 2u);
                    aN[r].w *= drop_factor(base + 3u);
                }
                As[nxt][acol + 0][arow + r * 64] = aN[r].x;
                As[nxt][acol + 1][arow + r * 64] = aN[r].y;
                As[nxt][acol + 2][arow + r * 64] = aN[r].z;
                As[nxt][acol + 3][arow + r * 64] = aN[r].w;
                *(float4*)&Bs[nxt][brow + r * 8][bcol] = bN[r];
            }
            __syncthreads();
        }
    }

    // epilogue: store h (fp16) + fused attention logits (fp32)
    float4 vs0 = *(const float4*)&att_src[tx];
    float4 vs1 = *(const float4*)&att_src[tx + 4];
    float4 vd0 = *(const float4*)&att_dst[tx];
    float4 vd1 = *(const float4*)&att_dst[tx + 4];
    const int lane = tid & 31;
    const int head = (lane & 15) >> 2;          // head of this thread's cols

#pragma unroll
    for (int i = 0; i < 8; i++) {
        int row = bm + ty + i;
        if (row < M) {
            __half2 p0 = __floats2half2_rn(acc[i][0], acc[i][1]);
            __half2 p1 = __floats2half2_rn(acc[i][2], acc[i][3]);
            __half2 p2 = __floats2half2_rn(acc[i][4], acc[i][5]);
            __half2 p3 = __floats2half2_rn(acc[i][6], acc[i][7]);
            uint4 u;
            u.x = *(unsigned*)&p0; u.y = *(unsigned*)&p1;
            u.z = *(unsigned*)&p2; u.w = *(unsigned*)&p3;
            *(uint4*)&g_hh[(size_t)row * 128 + tx] = u;
        }
        float s = acc[i][0] * vs0.x + acc[i][1] * vs0.y + acc[i][2] * vs0.z + acc[i][3] * vs0.w
                + acc[i][4] * vs1.x + acc[i][5] * vs1.y + acc[i][6] * vs1.z + acc[i][7] * vs1.w;
        float d = acc[i][0] * vd0.x + acc[i][1] * vd0.y + acc[i][2] * vd0.z + acc[i][3] * vd0.w
                + acc[i][4] * vd1.x + acc[i][5] * vd1.y + acc[i][6] * vd1.z + acc[i][7] * vd1.w;
        s += __shfl_xor_sync(0xFFFFFFFFu, s, 1);
        s += __shfl_xor_sync(0xFFFFFFFFu, s, 2);
        d += __shfl_xor_sync(0xFFFFFFFFu, d, 1);
        d += __shfl_xor_sync(0xFFFFFFFFu, d, 2);
        if ((lane & 3) == 0 && row < M) {
            g_as[row * 4 + head] = s;
            g_ad[row * 4 + head] = d;
        }
    }
}

// ---------------- fused aggregate + softmax-div + bias + PReLU --------------
// warp per dst node; fp16 h gathers; software-pipelined 16-edge batches.
__global__ void k_agg(const float* __restrict__ bias,
                      const float* __restrict__ prelu_a,
                      float* __restrict__ out, int n) {
    int gid  = blockIdx.x * blockDim.x + threadIdx.x;
    int node = gid >> 5;
    int lane = gid & 31;
    if (node >= n) return;

    const int start = g_rowptr[node];
    const int end   = g_rowptr[node + 1];
    const int sub   = lane >> 2;        // 0..7 : edge slot in batch
    const int hl    = lane & 3;         // head for logit compute
    const int hh    = lane >> 3;        // head of this lane's output cols

    const float adl = g_ad[node * 4 + hl];   // dst logit term for head hl

    float acc0 = 0.f, acc1 = 0.f, acc2 = 0.f, acc3 = 0.f;
    float den_p = 0.f;                  // partial denominator for head hl

    // current batch registers
    int   cs0 = 0, cs1 = 0;
    float ce0 = 0.f, ce1 = 0.f;

    // load batch at j into (s0,s1,e0,e1)
    auto load_batch = [&](int j, int& s0, int& s1, float& e0, float& e1) {
        int jj0 = j + sub, jj1 = j + 8 + sub;
        s0 = 0; s1 = 0; e0 = 0.f; e1 = 0.f;
        if (jj0 < end) {
            s0 = g_srcs[jj0];
            float ev = g_as[s0 * 4 + hl] + adl;
            ev = ev >= 0.f ? ev : 0.2f * ev;
            e0 = expf(ev);
        }
        if (jj1 < end) {
            s1 = g_srcs[jj1];
            float ev = g_as[s1 * 4 + hl] + adl;
            ev = ev >= 0.f ? ev : 0.2f * ev;
            e1 = expf(ev);
        }
    };

    load_batch(start, cs0, cs1, ce0, ce1);

    for (int j = start; j < end; j += 16) {
        // prefetch next batch while current gathers are in flight
        int   ns0 = 0, ns1 = 0;
        float ne0 = 0.f, ne1 = 0.f;
        if (j + 16 < end) load_batch(j + 16, ns0, ns1, ne0, ne1);

        den_p += ce0 + ce1;

#pragma unroll
        for (int b = 0; b < 8; b++) {
            float w = __shfl_sync(0xFFFFFFFFu, ce0, b * 4 + hh);
            int   s = __shfl_sync(0xFFFFFFFFu, cs0, b * 4);
            if (j + b < end) {
                uint2 hv = *(const uint2*)&g_hh[(size_t)s * HC + lane * 4];
                float2 f0 = __half22float2(*(__half2*)&hv.x);
                float2 f1 = __half22float2(*(__half2*)&hv.y);
                acc0 += w * f0.x; acc1 += w * f0.y; acc2 += w * f1.x; acc3 += w * f1.y;
            }
        }
#pragma unroll
        for (int b = 0; b < 8; b++) {
            float w = __shfl_sync(0xFFFFFFFFu, ce1, b * 4 + hh);
            int   s = __shfl_sync(0xFFFFFFFFu, cs1, b * 4);
            if (j + 8 + b < end) {
                uint2 hv = *(const uint2*)&g_hh[(size_t)s * HC + lane * 4];
                float2 f0 = __half22float2(*(__half2*)&hv.x);
                float2 f1 = __half22float2(*(__half2*)&hv.y);
                acc0 += w * f0.x; acc1 += w * f0.y; acc2 += w * f1.x; acc3 += w * f1.y;
            }
        }

        cs0 = ns0; cs1 = ns1; ce0 = ne0; ce1 = ne1;
    }

#pragma unroll
    for (int off = 16; off >= 4; off >>= 1)
        den_p += __shfl_xor_sync(0xFFFFFFFFu, den_p, off);
    float den = __shfl_sync(0xFFFFFFFFu, den_p, hh);
    float inv = 1.0f / fmaxf(den, 1e-16f);

    const float a = *prelu_a;
    float4 bv = *(const float4*)&bias[lane * 4];
    float4 o;
    o.x = acc0 * inv + bv.x;
    o.y = acc1 * inv + bv.y;
    o.z = acc2 * inv + bv.z;
    o.w = acc3 * inv + bv.w;
    o.x = o.x >= 0.f ? o.x : a * o.x;
    o.y = o.y >= 0.f ? o.y : a * o.y;
    o.z = o.z >= 0.f ? o.z : a * o.z;
    o.w = o.w >= 0.f ? o.w : a * o.w;
    *(float4*)&out[(size_t)node * HC + lane * 4] = o;
}

// ---------------- launch (stream-forked: CSR build ∥ GEMM) ----------------
extern "C" void kernel_launch(void* const* d_in, const int* in_sizes, int n_in,
                              void* d_out, int out_size) {
    const float* x        = (const float*)d_in[0];
    const float* W        = (const float*)d_in[1];
    const float* att_src  = (const float*)d_in[2];
    const float* att_dst  = (const float*)d_in[3];
    const float* bias     = (const float*)d_in[4];
    const float* prelu_a  = (const float*)d_in[5];
    const int*   ei       = (const int*)d_in[6];   // int32 (JAX x64 disabled)

    const int n  = in_sizes[0] / FIN;   // 50000
    const int E  = in_sizes[6] / 2;     // 1600000
    const int ET = E + n;
    float* out = (float*)d_out;

    // one-time stream/event creation (first call is the uncaptured correctness run)
    static cudaStream_t s_csr = nullptr;
    static cudaEvent_t  ev_fork = nullptr, ev_join = nullptr;
    if (s_csr == nullptr) {
        cudaStreamCreateWithFlags(&s_csr, cudaStreamNonBlocking);
        cudaEventCreateWithFlags(&ev_fork, cudaEventDisableTiming);
        cudaEventCreateWithFlags(&ev_join, cudaEventDisableTiming);
    }

    // fork: CSR build on s_csr, GEMM on the main (capture) stream
    cudaEventRecord(ev_fork, 0);
    cudaStreamWaitEvent(s_csr, ev_fork, 0);

    k_cnt_init<<<(n + 511) / 512, 512, 0, s_csr>>>(n);
    k_hist    <<<(E + 255) / 256, 256, 0, s_csr>>>(ei, E);
    k_scan    <<<1, 1024, 0, s_csr>>>(n);
    k_scatter <<<(ET + 255) / 256, 256, 0, s_csr>>>(ei, E, n);
    cudaEventRecord(ev_join, s_csr);

    k_gemm    <<<(n + 127) / 128, 256>>>(x, W, att_src, att_dst, n);

    // join: agg needs both CSR and h/as/ad
    cudaStreamWaitEvent(0, ev_join, 0);
    k_agg     <<<((long long)n * 32 + 255) / 256, 256>>>(bias, prelu_a, out, n);
}

// round 14
// speedup vs baseline: 1.1686x; 1.1686x over previous
#include <cuda_runtime.h>
#include <cuda_fp16.h>
#include <cstdint>

#define NN   50000
#define FIN  256
#define HH   4
#define HC   128
#define EMAX 1600000
#define ASTR 40   // smem row stride in halves (32 data + 8 pad)

// ---------------- scratch (static __device__, no allocations) ----------------
__device__ float g_h [(size_t)NN * HC];  // dropout(x) @ W  (25.6 MB, fp32)
__device__ float g_as[NN * HH];          // <h, att_src>
__device__ float g_ad[NN * HH];          // <h, att_dst>
__device__ int   g_rowptr[NN + 1];       // CSR row pointers (by dst)
__device__ int   g_cnt[NN];              // degree counters / write cursors
__device__ int   g_srcs[EMAX + NN];      // CSR: src node per incoming edge

// JAX partitionable threefry dropout factor for element index i:
// (b1,b2) = threefry2x32(key=(0,1), x0=0, x1=i); bits = b1^b2
__device__ __forceinline__ float drop_factor(unsigned i) {
    unsigned x0 = 0u, x1 = i;
    const unsigned ks0 = 0u, ks1 = 1u, ks2 = 0x1BD11BDBu;
    x0 += ks0; x1 += ks1;
#define TF_R(r) { x0 += x1; x1 = (x1 << (r)) | (x1 >> (32 - (r))); x1 ^= x0; }
    TF_R(13) TF_R(15) TF_R(26) TF_R(6)   x0 += ks1; x1 += ks2 + 1u;
    TF_R(17) TF_R(29) TF_R(16) TF_R(24)  x0 += ks2; x1 += ks0 + 2u;
    TF_R(13) TF_R(15) TF_R(26) TF_R(6)   x0 += ks0; x1 += ks1 + 3u;
    TF_R(17) TF_R(29) TF_R(16) TF_R(24)  x0 += ks1; x1 += ks2 + 4u;
    TF_R(13) TF_R(15) TF_R(26) TF_R(6)   x0 += ks2; x1 += ks0 + 5u;
#undef TF_R
    unsigned bits = x0 ^ x1;
    float u = __uint_as_float((bits >> 9) | 0x3F800000u) - 1.0f;
    return (u < 0.8f) ? 1.25f : 0.0f;
}

// ---------------- CSR build ----------------
__global__ void k_cnt_init(int n) {
    int i = blockIdx.x * blockDim.x + threadIdx.x;
    if (i < n) g_cnt[i] = 1;             // 1 = the self-loop
}
__global__ void k_hist(const int* __restrict__ ei, int E) {
    int e = blockIdx.x * blockDim.x + threadIdx.x;
    if (e < E) atomicAdd(&g_cnt[ei[E + e]], 1);
}
__global__ void k_scan(int n) {
    __shared__ int part[1024];
    const int tid = threadIdx.x;
    const int chunk = (n + 1023) / 1024;
    const int lo = tid * chunk;
    const int hi = min(lo + chunk, n);
    int sum = 0;
    for (int i = lo; i < hi; i++) sum += g_cnt[i];
    part[tid] = sum;
    __syncthreads();
    for (int off = 1; off < 1024; off <<= 1) {
        int v = 0;
        if (tid >= off) v = part[tid - off];
        __syncthreads();
        if (tid >= off) part[tid] += v;
        __syncthreads();
    }
    int run = (tid == 0) ? 0 : part[tid - 1];
    for (int i = lo; i < hi; i++) {
        int c = g_cnt[i];
        g_rowptr[i] = run;
        g_cnt[i]    = run;
        run += c;
    }
    if (tid == 1023) g_rowptr[n] = part[1023];
}
__global__ void k_scatter(const int* __restrict__ ei, int E, int n) {
    int e = blockIdx.x * blockDim.x + threadIdx.x;
    if (e >= E + n) return;
    int s, d;
    if (e < E) { s = ei[e]; d = ei[E + e]; }
    else       { s = d = e - E; }
    int pos = atomicAdd(&g_cnt[d], 1);
    g_srcs[pos] = s;
}

// ---------------- mma helper ----------------
__device__ __forceinline__ void mma16816(float* c, const unsigned* a, const unsigned* b) {
    asm volatile(
        "mma.sync.aligned.m16n8k16.row.col.f32.f16.f16.f32 "
        "{%0,%1,%2,%3}, {%4,%5,%6,%7}, {%8,%9}, {%0,%1,%2,%3};\n"
        : "+f"(c[0]), "+f"(c[1]), "+f"(c[2]), "+f"(c[3])
        : "r"(a[0]), "r"(a[1]), "r"(a[2]), "r"(a[3]), "r"(b[0]), "r"(b[1]));
}

// ---------------- tensor-core GEMM: fused threefry dropout + att logits -----
// h = dropout(x) @ W  (fp16 inputs, fp32 accum).  Block 128x128, K=256.
// 8 warps: warp_m = wid>>2 (64 rows), warp_n = wid&3 (32 cols = head warp_n).
__global__ void k_gemm(const float* __restrict__ X, const float* __restrict__ W,
                       const float* __restrict__ att_src,
                       const float* __restrict__ att_dst, int M) {
    __shared__ __half As[2][128 * ASTR];
    __shared__ __half Bs[2][128 * ASTR];

    const int tid  = threadIdx.x;
    const int wid  = tid >> 5;
    const int lane = tid & 31;
    const int g    = lane >> 2;     // group 0..7
    const int t    = lane & 3;      // thread-in-group
    const int warp_m = wid >> 2;    // 0..1
    const int warp_n = wid & 3;     // 0..3 == head
    const int bm = blockIdx.x * 128;

    // loader mapping
    const int lrow = tid >> 1;            // 0..127 (A row)
    const int lkb  = (tid & 1) * 16;      // k-half offset within chunk
    const int grow = bm + lrow;
    const int wkp  = tid >> 4;            // 0..15 (W k-pair)
    const int wnb  = (tid & 15) * 8;      // W n base

    float acc[4][4][4];
#pragma unroll
    for (int mi = 0; mi < 4; mi++)
#pragma unroll
        for (int ni = 0; ni < 4; ni++)
#pragma unroll
            for (int q = 0; q < 4; q++) acc[mi][ni][q] = 0.0f;

    float4 xv[4], wv[4];

    // ---- gmem load of chunk c into regs ----
    auto load_gmem = [&](int c) {
        const int k0 = c * 32;
#pragma unroll
        for (int j = 0; j < 4; j++) {
            xv[j] = make_float4(0.f, 0.f, 0.f, 0.f);
            if (grow < M) xv[j] = *(const float4*)&X[(size_t)grow * 256 + k0 + lkb + j * 4];
        }
        const int k = k0 + wkp * 2;
        wv[0] = *(const float4*)&W[(size_t)k * 128 + wnb];
        wv[1] = *(const float4*)&W[(size_t)k * 128 + wnb + 4];
        wv[2] = *(const float4*)&W[(size_t)(k + 1) * 128 + wnb];
        wv[3] = *(const float4*)&W[(size_t)(k + 1) * 128 + wnb + 4];
    };

    // ---- regs -> smem (dropout applied to A here, then fp16 convert) ----
    auto store_smem = [&](int buf, int c) {
        const int k0 = c * 32;
#pragma unroll
        for (int j = 0; j < 4; j++) {
            float4 v = xv[j];
            if (grow < M) {
                unsigned base = (unsigned)grow * 256u + (unsigned)(k0 + lkb + j * 4);
                v.x *= drop_factor(base + 0u);
                v.y *= drop_factor(base + 1u);
                v.z *= drop_factor(base + 2u);
                v.w *= drop_factor(base + 3u);
            }
            __half2* p = (__half2*)&As[buf][lrow * ASTR + lkb + j * 4];
            p[0] = __floats2half2_rn(v.x, v.y);
            p[1] = __floats2half2_rn(v.z, v.w);
        }
        const float* p0 = (const float*)&wv[0];
        const float* p1 = (const float*)&wv[1];
        const float* p2 = (const float*)&wv[2];
        const float* p3 = (const float*)&wv[3];
#pragma unroll
        for (int i = 0; i < 4; i++) {
            *(__half2*)&Bs[buf][(wnb + i)     * ASTR + wkp * 2] = __floats2half2_rn(p0[i], p2[i]);
            *(__half2*)&Bs[buf][(wnb + i + 4) * ASTR + wkp * 2] = __floats2half2_rn(p1[i], p3[i]);
        }
    };

    // ---- mma over one 32-wide K chunk in smem ----
    auto mma_chunk = [&](int buf) {
#pragma unroll
        for (int ks = 0; ks < 2; ks++) {
            unsigned a[4][4], b[4][2];
#pragma unroll
            for (int mi = 0; mi < 4; mi++) {
                const int row = warp_m * 64 + mi * 16 + g;
                const __half* base = &As[buf][row * ASTR + ks * 16 + 2 * t];
                a[mi][0] = *(const unsigned*)(base);
                a[mi][1] = *(const unsigned*)(base + 8 * ASTR);
                a[mi][2] = *(const unsigned*)(base + 8);
                a[mi][3] = *(const unsigned*)(base + 8 * ASTR + 8);
            }
#pragma unroll
            for (int ni = 0; ni < 4; ni++) {
                const int n = warp_n * 32 + ni * 8 + g;
                const __half* base = &Bs[buf][n * ASTR + ks * 16 + 2 * t];
                b[ni][0] = *(const unsigned*)(base);
                b[ni][1] = *(const unsigned*)(base + 8);
            }
#pragma unroll
            for (int mi = 0; mi < 4; mi++)
#pragma unroll
                for (int ni = 0; ni < 4; ni++)
                    mma16816(acc[mi][ni], a[mi], b[ni]);
        }
    };

    load_gmem(0);
    store_smem(0, 0);
    __syncthreads();

    for (int c = 0; c < 8; c++) {
        if (c < 7) load_gmem(c + 1);
        mma_chunk(c & 1);
        if (c < 7) {
            store_smem((c + 1) & 1, c + 1);
            __syncthreads();
        }
    }

    // ---- epilogue: store h (fp32) + per-head attention logits ----
    float asv[4][2], adv[4][2];
#pragma unroll
    for (int ni = 0; ni < 4; ni++) {
        const int col = warp_n * 32 + ni * 8 + 2 * t;
        asv[ni][0] = att_src[col];     asv[ni][1] = att_src[col + 1];
        adv[ni][0] = att_dst[col];     adv[ni][1] = att_dst[col + 1];
    }

#pragma unroll
    for (int mi = 0; mi < 4; mi++) {
        const int row_lo = bm + warp_m * 64 + mi * 16 + g;
        const int row_hi = row_lo + 8;
        float s_lo = 0.f, d_lo = 0.f, s_hi = 0.f, d_hi = 0.f;
#pragma unroll
        for (int ni = 0; ni < 4; ni++) {
            const int col = warp_n * 32 + ni * 8 + 2 * t;
            s_lo += acc[mi][ni][0] * asv[ni][0] + acc[mi][ni][1] * asv[ni][1];
            d_lo += acc[mi][ni][0] * adv[ni][0] + acc[mi][ni][1] * adv[ni][1];
            s_hi += acc[mi][ni][2] * asv[ni][0] + acc[mi][ni][3] * asv[ni][1];
            d_hi += acc[mi][ni][2] * adv[ni][0] + acc[mi][ni][3] * adv[ni][1];
            if (row_lo < M) {
                float2 v = make_float2(acc[mi][ni][0], acc[mi][ni][1]);
                *(float2*)&g_h[(size_t)row_lo * 128 + col] = v;
            }
            if (row_hi < M) {
                float2 v = make_float2(acc[mi][ni][2], acc[mi][ni][3]);
                *(float2*)&g_h[(size_t)row_hi * 128 + col] = v;
            }
        }
        // reduce over the 4 threads of the group (t = 0..3)
        s_lo += __shfl_xor_sync(0xFFFFFFFFu, s_lo, 1);
        s_lo += __shfl_xor_sync(0xFFFFFFFFu, s_lo, 2);
        d_lo += __shfl_xor_sync(0xFFFFFFFFu, d_lo, 1);
        d_lo += __shfl_xor_sync(0xFFFFFFFFu, d_lo, 2);
        s_hi += __shfl_xor_sync(0xFFFFFFFFu, s_hi, 1);
        s_hi += __shfl_xor_sync(0xFFFFFFFFu, s_hi, 2);
        d_hi += __shfl_xor_sync(0xFFFFFFFFu, d_hi, 1);
        d_hi += __shfl_xor_sync(0xFFFFFFFFu, d_hi, 2);
        if (t == 0) {
            if (row_lo < M) { g_as[row_lo * 4 + warp_n] = s_lo; g_ad[row_lo * 4 + warp_n] = d_lo; }
            if (row_hi < M) { g_as[row_hi * 4 + warp_n] = s_hi; g_ad[row_hi * 4 + warp_n] = d_hi; }
        }
    }
}

// ---------------- fused aggregate + softmax-div + bias + PReLU --------------
// warp per dst node; 16-edge batches, fully unrolled predicated gathers (fp32).
__global__ void k_agg(const float* __restrict__ bias,
                      const float* __restrict__ prelu_a,
                      float* __restrict__ out, int n) {
    int gid  = blockIdx.x * blockDim.x + threadIdx.x;
    int node = gid >> 5;
    int lane = gid & 31;
    if (node >= n) return;

    const int start = g_rowptr[node];
    const int end   = g_rowptr[node + 1];
    const int sub   = lane >> 2;
    const int hl    = lane & 3;
    const int hh    = lane >> 3;

    const float adl = g_ad[node * 4 + hl];

    float acc0 = 0.f, acc1 = 0.f, acc2 = 0.f, acc3 = 0.f;
    float den_p = 0.f;

    for (int j = start; j < end; j += 16) {
        int   jj0 = j + sub,      jj1 = j + 8 + sub;
        float ee0 = 0.f, ee1 = 0.f;
        int   sE0 = 0,   sE1 = 0;
        if (jj0 < end) {
            sE0 = g_srcs[jj0];
            float ev = g_as[sE0 * 4 + hl] + adl;
            ev = ev >= 0.f ? ev : 0.2f * ev;
            ee0 = expf(ev);
        }
        if (jj1 < end) {
            sE1 = g_srcs[jj1];
            float ev = g_as[sE1 * 4 + hl] + adl;
            ev = ev >= 0.f ? ev : 0.2f * ev;
            ee1 = expf(ev);
        }
        den_p += ee0 + ee1;

#pragma unroll
        for (int b = 0; b < 8; b++) {
            float w = __shfl_sync(0xFFFFFFFFu, ee0, b * 4 + hh);
            int   s = __shfl_sync(0xFFFFFFFFu, sE0, b * 4);
            if (j + b < end) {
                float4 hv = *(const float4*)&g_h[(size_t)s * HC + lane * 4];
                acc0 += w * hv.x; acc1 += w * hv.y; acc2 += w * hv.z; acc3 += w * hv.w;
            }
        }
#pragma unroll
        for (int b = 0; b < 8; b++) {
            float w = __shfl_sync(0xFFFFFFFFu, ee1, b * 4 + hh);
            int   s = __shfl_sync(0xFFFFFFFFu, sE1, b * 4);
            if (j + 8 + b < end) {
                float4 hv = *(const float4*)&g_h[(size_t)s * HC + lane * 4];
                acc0 += w * hv.x; acc1 += w * hv.y; acc2 += w * hv.z; acc3 += w * hv.w;
            }
        }
    }

#pragma unroll
    for (int off = 16; off >= 4; off >>= 1)
        den_p += __shfl_xor_sync(0xFFFFFFFFu, den_p, off);
    float den = __shfl_sync(0xFFFFFFFFu, den_p, hh);
    float inv = 1.0f / fmaxf(den, 1e-16f);

    const float a = *prelu_a;
    float4 bv = *(const float4*)&bias[lane * 4];
    float4 o;
    o.x = acc0 * inv + bv.x;
    o.y = acc1 * inv + bv.y;
    o.z = acc2 * inv + bv.z;
    o.w = acc3 * inv + bv.w;
    o.x = o.x >= 0.f ? o.x : a * o.x;
    o.y = o.y >= 0.f ? o.y : a * o.y;
    o.z = o.z >= 0.f ? o.z : a * o.z;
    o.w = o.w >= 0.f ? o.w : a * o.w;
    *(float4*)&out[(size_t)node * HC + lane * 4] = o;
}

// ---------------- launch (stream-forked: CSR build ∥ GEMM) ----------------
extern "C" void kernel_launch(void* const* d_in, const int* in_sizes, int n_in,
                              void* d_out, int out_size) {
    const float* x        = (const float*)d_in[0];
    const float* W        = (const float*)d_in[1];
    const float* att_src  = (const float*)d_in[2];
    const float* att_dst  = (const float*)d_in[3];
    const float* bias     = (const float*)d_in[4];
    const float* prelu_a  = (const float*)d_in[5];
    const int*   ei       = (const int*)d_in[6];   // int32 (JAX x64 disabled)

    const int n  = in_sizes[0] / FIN;   // 50000
    const int E  = in_sizes[6] / 2;     // 1600000
    const int ET = E + n;
    float* out = (float*)d_out;

    static cudaStream_t s_csr = nullptr;
    static cudaEvent_t  ev_fork = nullptr, ev_join = nullptr;
    if (s_csr == nullptr) {
        cudaStreamCreateWithFlags(&s_csr, cudaStreamNonBlocking);
        cudaEventCreateWithFlags(&ev_fork, cudaEventDisableTiming);
        cudaEventCreateWithFlags(&ev_join, cudaEventDisableTiming);
    }

    cudaEventRecord(ev_fork, 0);
    cudaStreamWaitEvent(s_csr, ev_fork, 0);

    k_cnt_init<<<(n + 511) / 512, 512, 0, s_csr>>>(n);
    k_hist    <<<(E + 255) / 256, 256, 0, s_csr>>>(ei, E);
    k_scan    <<<1, 1024, 0, s_csr>>>(n);
    k_scatter <<<(ET + 255) / 256, 256, 0, s_csr>>>(ei, E, n);
    cudaEventRecord(ev_join, s_csr);

    k_gemm    <<<(n + 127) / 128, 256>>>(x, W, att_src, att_dst, n);

    cudaStreamWaitEvent(0, ev_join, 0);
    k_agg     <<<((long long)n * 32 + 255) / 256, 256>>>(bias, prelu_a, out, n);
}